// round 14
// baseline (speedup 1.0000x reference)
#include <cuda_runtime.h>

// T=256, BS=128, N=2048. One persistent CTA per batch lane.
// 8 warps x 4 packed pairs/thread; symmetric replicated scalar tail.
#define T_STEPS 256
#define BSZ     128
#define NFEAT   2048
#define BLOCK   256
#define EPT     8                  // elements per thread
#define PAIRS   (EPT / 2)          // 4 packed f32x2 pairs
#define NWARP   (BLOCK / 32)       // 8 warps
#define NPART   (2 * NWARP)        // 16 partials (4-level butterfly, lanes 0-1)
#define FUDGE_C 1e-4f

typedef unsigned long long ull;

static __device__ __forceinline__ ull pack2(float lo, float hi) {
    ull r; asm("mov.b64 %0, {%1, %2};" : "=l"(r) : "f"(lo), "f"(hi)); return r;
}
static __device__ __forceinline__ ull bcast2(float v) { return pack2(v, v); }
static __device__ __forceinline__ float2 unpack2(ull v) {
    float2 r; asm("mov.b64 {%0, %1}, %2;" : "=f"(r.x), "=f"(r.y) : "l"(v)); return r;
}
static __device__ __forceinline__ ull fma2(ull a, ull b, ull c) {
    ull d; asm("fma.rn.f32x2 %0, %1, %2, %3;" : "=l"(d) : "l"(a), "l"(b), "l"(c)); return d;
}
static __device__ __forceinline__ ull add2(ull a, ull b) {
    ull d; asm("add.rn.f32x2 %0, %1, %2;" : "=l"(d) : "l"(a), "l"(b)); return d;
}
static __device__ __forceinline__ ull relu2(ull v) {
    float2 f = unpack2(v);
    return pack2(fmaxf(f.x, 0.0f), fmaxf(f.y, 0.0f));
}

__global__ __launch_bounds__(BLOCK, 1)
void elbo_scan_kernel(const float* __restrict__ noises,   // [T,BS]
                      const float* __restrict__ ys,       // [T,BS]
                      const float* __restrict__ qs,       // [T,BS]
                      const float* __restrict__ z_biases, // [N]
                      const float* __restrict__ w_in,     // [N]
                      const float* __restrict__ w_inq,    // [N]
                      const float* __restrict__ p_llr,
                      const float* __restrict__ p_llrd,
                      const float* __restrict__ p_sigb,
                      const float* __restrict__ p_os,
                      const float* __restrict__ p_ufs,
                      const float* __restrict__ p_spwd,
                      const float* __restrict__ p_qsc,
                      const float* __restrict__ p_tq,
                      const float* __restrict__ p_ty,
                      const float* __restrict__ p_te,
                      float* __restrict__ out)            // [T,BS]
{
    const int b    = blockIdx.x;
    const int tid  = threadIdx.x;
    const int wid  = tid >> 5;
    const int lane = tid & 31;

    __shared__ float s_y[T_STEPS];
    __shared__ float s_n[T_STEPS];
    __shared__ float s_q[T_STEPS];
    __shared__ ull   s_p[2][NPART];    // double-buffered packed (au,ah) partials

    s_y[tid] = ys[tid * BSZ + b];
    s_n[tid] = noises[tid * BSZ + b];
    s_q[tid] = qs[tid * BSZ + b];

    const float lr0   = expf(p_llr[0]);
    const float lrd   = expf(p_llrd[0]);
    const float sigb  = p_sigb[0];
    const float osc   = p_os[0];
    const float ufsm1 = p_ufs[0] - 1.0f;
    const float spwd  = log1pf(expf(p_spwd[0]));
    const float qsc   = p_qsc[0];
    const float tq    = 1.0f + log1pf(expf(p_tq[0]));
    const float ty    = 1.0f + log1pf(expf(p_ty[0]));
    const float te    = 1.0f + log1pf(expf(p_te[0]));
    const float itq = 1.0f / tq, ctq = 1.0f - itq;
    const float ity = 1.0f / ty, cty = 1.0f - ity;
    const float ite = 1.0f / te, cte = 1.0f - ite;

    // Register-resident per-thread slices, packed f32x2.
    ull win2[PAIRS], wiq2[PAIRS], bia2[PAIRS], W2[PAIRS], A2[PAIRS], hv[PAIRS];
    {
        const int base = tid * EPT;
        const float4* w4 = reinterpret_cast<const float4*>(w_in + base);
        const float4* q4 = reinterpret_cast<const float4*>(w_inq + base);
        const float4* z4 = reinterpret_cast<const float4*>(z_biases + base);
        #pragma unroll
        for (int v = 0; v < EPT / 4; ++v) {
            float4 a = w4[v], c = q4[v], z = z4[v];
            win2[2*v]   = pack2(a.x, a.y);  win2[2*v+1] = pack2(a.z, a.w);
            wiq2[2*v]   = pack2(c.x, c.y);  wiq2[2*v+1] = pack2(c.z, c.w);
            bia2[2*v]   = pack2(sigb * z.x, sigb * z.y);
            bia2[2*v+1] = pack2(sigb * z.z, sigb * z.w);
        }
    }
    #pragma unroll
    for (int k = 0; k < PAIRS; ++k) W2[k] = 0ull;

    __syncthreads();   // staged inputs visible

    // ---------------- Prologue: step-0 partials + coefs for iteration 0 ----------------
    float lrmult = 1.0f, ylp = 0.0f;
    float lr_c = lr0;                                  // lr_t
    float cW   = 1.0f;                                 // cW_t
    float cWn  = fmaf(-lr_c, spwd, 1.0f);              // cW_{t+1}
    float icWn = __fdividef(1.0f, cWn);                // 1/cW_{t+1}
    float qlp  = s_q[0] * itq;
    {
        const ull x2  = bcast2(s_n[0]);                // x_0 = noise_0 (u=e=0)
        const ull cq2 = bcast2(qsc * qlp);
        ull ah0 = 0ull, ah1 = 0ull;
        #pragma unroll
        for (int k = 0; k < PAIRS; ++k) {
            ull h = relu2(fma2(win2[k], x2, fma2(cq2, wiq2[k], bia2[k])));
            hv[k] = h;
            if (k & 1) ah1 = fma2(h, h, ah1); else ah0 = fma2(h, h, ah0);
        }
        float2 f2 = unpack2(add2(ah0, ah1));
        float ah_s = f2.x + f2.y;
        float au_s = 0.0f;
        #pragma unroll
        for (int off = 16; off >= 2; off >>= 1) {
            au_s += __shfl_xor_sync(0xFFFFFFFFu, au_s, off);
            ah_s += __shfl_xor_sync(0xFFFFFFFFu, ah_s, off);
        }
        if (lane < 2) s_p[0][(wid << 1) | lane] = pack2(au_s, ah_s);  // au_0 = 0
    }
    // Coefficients for iteration 0 (step-0 consumption; ylp_{-1}=elp_{-1}=0).
    float y_c    = s_y[0];
    bool  flag_c = ((__float_as_uint(y_c) & 0x7FFFFFFFu) > 0x7F800000u);
    float byl_c  = 0.0f;
    float axc_c  = (ufsm1 + (flag_c ? ity : 0.0f)) * cW;
    float be_c   = flag_c ? 0.0f : ity * y_c;
    float bx_c   = be_c + s_n[1];
    float aec_c  = (flag_c ? (ity - 1.0f) : -1.0f) * cW;
    float belp_c = 0.0f;
    float lic_c  = lr_c * icWn;
    float elp    = 0.0f;
    // cq for step 1 (A2 prep happens at loop top, in the LDS shadow).
    qlp = fmaf(ctq, qlp, s_q[1] * itq);
    ull cq2_c = bcast2(qsc * qlp);

    __syncthreads();   // s_p[0] visible; NOTHING between STS and this bar

    #pragma unroll 2
    for (int t = 0; t < T_STEPS; ++t) {
        const int buf = t & 1;

        // --- Combine step-t partials (8 LDS.128 first; A2 prep fills the wait). ---
        const longlong2* pp = reinterpret_cast<const longlong2*>(s_p[buf]);
        longlong2 l0 = pp[0], l1 = pp[1], l2 = pp[2], l3 = pp[3];
        longlong2 l4 = pp[4], l5 = pp[5], l6 = pp[6], l7 = pp[7];

        #pragma unroll
        for (int k = 0; k < PAIRS; ++k) A2[k] = fma2(cq2_c, wiq2[k], bia2[k]);

        ull r0 = add2(add2((ull)l0.x, (ull)l0.y), add2((ull)l1.x, (ull)l1.y));
        ull r1 = add2(add2((ull)l2.x, (ull)l2.y), add2((ull)l3.x, (ull)l3.y));
        ull r2 = add2(add2((ull)l4.x, (ull)l4.y), add2((ull)l5.x, (ull)l5.y));
        ull r3 = add2(add2((ull)l6.x, (ull)l6.y), add2((ull)l7.x, (ull)l7.y));
        float2 s = unpack2(add2(add2(r0, r1), add2(r2, r3)));
        const float sumu = s.x, sumh = s.y;

        // --- Short affine chains off sumu (coefs prepped last iteration). ---
        const float en   = fmaf(aec_c, sumu, be_c);     // e_t
        const float elpn = fmaf(ite, en, belp_c);       // elp_t
        const ull leoc2  = bcast2(lic_c * elpn);        // W-update coeff
        const ull x2     = bcast2(fmaf(axc_c, sumu, bx_c));   // x_{t+1}

        // --- Hot loop: W_{t+1}, h_{t+1}, partial dot/sumsq (fused). ---
        ull au0 = 0ull, au1 = 0ull, ah0 = 0ull, ah1 = 0ull;
        #pragma unroll
        for (int k = 0; k < PAIRS; ++k) {
            W2[k] = fma2(leoc2, hv[k], W2[k]);
            ull h = relu2(fma2(win2[k], x2, A2[k]));
            hv[k] = h;
            if (k & 1) { au1 = fma2(W2[k], h, au1); ah1 = fma2(h, h, ah1); }
            else       { au0 = fma2(W2[k], h, au0); ah0 = fma2(h, h, ah0); }
        }
        float2 auf = unpack2(add2(au0, au1));
        float2 ahf = unpack2(add2(ah0, ah1));
        float au_s = auf.x + auf.y;
        float ah_s = ahf.x + ahf.y;

        // --- 4-level butterfly; lanes 0/1 hold parity halves. ---
        #pragma unroll
        for (int off = 16; off >= 2; off >>= 1) {
            au_s += __shfl_xor_sync(0xFFFFFFFFu, au_s, off);
            ah_s += __shfl_xor_sync(0xFFFFFFFFu, ah_s, off);
        }

        // --- Tail (replicated; fills the shfl shadow, overlapped across 2 warps/SMSP). ---
        const float un = cW * sumu;                     // u_t
        if (tid == 0) out[t * BSZ + b] = osc * un;
        const float ysel = flag_c ? un : y_c;
        ylp = fmaf(ity, ysel, byl_c);                   // ylp_t
        const float le = lr_c * elpn;
        const float v  = fmaf(le * le, sumh, FUDGE_C);
        lrmult *= __expf(-lrd * (v * __frsqrt_rn(v)));  // exp(-lrd*sqrt(v))
        lr_c = lr0 * lrmult;                            // lr_{t+1}
        cW   = cWn;                                     // cW_{t+1}
        cWn  = cW * fmaf(-lr_c, spwd, 1.0f);            // cW_{t+2}
        icWn = __fdividef(1.0f, cWn);
        elp  = elpn;
        // Coefficients for iteration t+1 (step t+1 consumption).
        const int ti = (t + 1 < T_STEPS) ? (t + 1) : t;
        const int tn = (t + 2 < T_STEPS) ? (t + 2) : (T_STEPS - 1);
        y_c    = s_y[ti];
        flag_c = ((__float_as_uint(y_c) & 0x7FFFFFFFu) > 0x7F800000u);
        byl_c  = cty * ylp;
        axc_c  = (ufsm1 + (flag_c ? ity : 0.0f)) * cW;
        be_c   = (flag_c ? 0.0f : ity * y_c) + byl_c;
        bx_c   = be_c + s_n[tn];
        aec_c  = (flag_c ? (ity - 1.0f) : -1.0f) * cW;
        belp_c = cte * elpn;
        lic_c  = lr_c * icWn;
        qlp    = fmaf(ctq, qlp, s_q[tn] * itq);         // qlp_{t+2}
        cq2_c  = bcast2(qsc * qlp);

        // --- STS then bar: nothing between them. ---
        if (lane < 2) s_p[buf ^ 1][(wid << 1) | lane] = pack2(au_s, ah_s);
        __syncthreads();
    }
}

extern "C" void kernel_launch(void* const* d_in, const int* in_sizes, int n_in,
                              void* d_out, int out_size)
{
    const float* noises = (const float*)d_in[1];
    const float* ys     = (const float*)d_in[2];
    const float* qs     = (const float*)d_in[3];
    const float* zb     = (const float*)d_in[4];
    const float* w_in   = (const float*)d_in[5];
    const float* w_inq  = (const float*)d_in[6];

    elbo_scan_kernel<<<BSZ, BLOCK>>>(noises, ys, qs, zb, w_in, w_inq,
                                     (const float*)d_in[7],  (const float*)d_in[8],
                                     (const float*)d_in[9],  (const float*)d_in[10],
                                     (const float*)d_in[11], (const float*)d_in[12],
                                     (const float*)d_in[13], (const float*)d_in[14],
                                     (const float*)d_in[15], (const float*)d_in[16],
                                     (float*)d_out);
}

// round 16
// speedup vs baseline: 1.5711x; 1.5711x over previous
#include <cuda_runtime.h>

// T=256, BS=128, N=2048. One persistent CTA per batch lane.
// 4 warps x 8 packed pairs/thread; replicated lean scalar tail.
#define T_STEPS 256
#define BSZ     128
#define NFEAT   2048
#define BLOCK   128
#define EPT     16                 // elements per thread
#define PAIRS   (EPT / 2)          // 8 packed f32x2 pairs
#define NWARP   (BLOCK / 32)       // 4 warps
#define NPART   (4 * NWARP)        // 16 partials (3-level butterfly, lanes 0-3)
#define FUDGE_C 1e-4f

typedef unsigned long long ull;

static __device__ __forceinline__ ull pack2(float lo, float hi) {
    ull r; asm("mov.b64 %0, {%1, %2};" : "=l"(r) : "f"(lo), "f"(hi)); return r;
}
static __device__ __forceinline__ ull bcast2(float v) { return pack2(v, v); }
static __device__ __forceinline__ float2 unpack2(ull v) {
    float2 r; asm("mov.b64 {%0, %1}, %2;" : "=f"(r.x), "=f"(r.y) : "l"(v)); return r;
}
static __device__ __forceinline__ ull fma2(ull a, ull b, ull c) {
    ull d; asm("fma.rn.f32x2 %0, %1, %2, %3;" : "=l"(d) : "l"(a), "l"(b), "l"(c)); return d;
}
static __device__ __forceinline__ ull add2(ull a, ull b) {
    ull d; asm("add.rn.f32x2 %0, %1, %2;" : "=l"(d) : "l"(a), "l"(b)); return d;
}
static __device__ __forceinline__ ull relu2(ull v) {
    float2 f = unpack2(v);
    return pack2(fmaxf(f.x, 0.0f), fmaxf(f.y, 0.0f));
}

__global__ __launch_bounds__(BLOCK, 1)
void elbo_scan_kernel(const float* __restrict__ noises,   // [T,BS]
                      const float* __restrict__ ys,       // [T,BS]
                      const float* __restrict__ qs,       // [T,BS]
                      const float* __restrict__ z_biases, // [N]
                      const float* __restrict__ w_in,     // [N]
                      const float* __restrict__ w_inq,    // [N]
                      const float* __restrict__ p_llr,
                      const float* __restrict__ p_llrd,
                      const float* __restrict__ p_sigb,
                      const float* __restrict__ p_os,
                      const float* __restrict__ p_ufs,
                      const float* __restrict__ p_spwd,
                      const float* __restrict__ p_qsc,
                      const float* __restrict__ p_tq,
                      const float* __restrict__ p_ty,
                      const float* __restrict__ p_te,
                      float* __restrict__ out)            // [T,BS]
{
    const int b    = blockIdx.x;
    const int tid  = threadIdx.x;
    const int wid  = tid >> 5;
    const int lane = tid & 31;

    __shared__ float  s_n[T_STEPS + 2];
    __shared__ float  s_q[T_STEPS + 2];
    __shared__ float4 s_yc[T_STEPS + 2];   // {ay, ae, by, fi} per step (y-derived)
    __shared__ ull    s_p[2][NPART];       // double-buffered packed (au,ah) partials

    const float lr0   = expf(p_llr[0]);
    const float lrd   = expf(p_llrd[0]);
    const float sigb  = p_sigb[0];
    const float osc   = p_os[0];
    const float ufsm1 = p_ufs[0] - 1.0f;
    const float spwd  = log1pf(expf(p_spwd[0]));
    const float qsc   = p_qsc[0];
    const float tq    = 1.0f + log1pf(expf(p_tq[0]));
    const float ty    = 1.0f + log1pf(expf(p_ty[0]));
    const float te    = 1.0f + log1pf(expf(p_te[0]));
    const float itq = 1.0f / tq, ctq = 1.0f - itq;
    const float ity = 1.0f / ty, cty = 1.0f - ity;
    const float ite = 1.0f / te, cte = 1.0f - ite;

    // Stage inputs + y-derived coefficient table (padded by 2; pads replicate T-1).
    {
        auto stage = [&](int t, int src) {
            const float y  = ys[src * BSZ + b];
            const bool fl  = ((__float_as_uint(y) & 0x7FFFFFFFu) > 0x7F800000u);
            s_yc[t] = make_float4(ufsm1 + (fl ? ity : 0.0f),      // ay
                                  fl ? (ity - 1.0f) : -1.0f,      // ae
                                  fl ? 0.0f : ity * y,            // by
                                  fl ? ity : 0.0f);               // fi
            s_n[t] = noises[src * BSZ + b];
            s_q[t] = qs[src * BSZ + b];
        };
        stage(tid, tid);
        stage(tid + BLOCK, tid + BLOCK);
        if (tid < 2) stage(T_STEPS + tid, T_STEPS - 1);
    }

    // Register-resident per-thread slices, packed f32x2.
    ull win2[PAIRS], wiq2[PAIRS], bia2[PAIRS], W2[PAIRS], A2[PAIRS], hv[PAIRS];
    {
        const int base = tid * EPT;
        const float4* w4 = reinterpret_cast<const float4*>(w_in + base);
        const float4* q4 = reinterpret_cast<const float4*>(w_inq + base);
        const float4* z4 = reinterpret_cast<const float4*>(z_biases + base);
        #pragma unroll
        for (int v = 0; v < EPT / 4; ++v) {
            float4 a = w4[v], c = q4[v], z = z4[v];
            win2[2*v]   = pack2(a.x, a.y);  win2[2*v+1] = pack2(a.z, a.w);
            wiq2[2*v]   = pack2(c.x, c.y);  wiq2[2*v+1] = pack2(c.z, c.w);
            bia2[2*v]   = pack2(sigb * z.x, sigb * z.y);
            bia2[2*v+1] = pack2(sigb * z.z, sigb * z.w);
        }
    }
    #pragma unroll
    for (int k = 0; k < PAIRS; ++k) W2[k] = 0ull;

    __syncthreads();   // staged inputs visible

    // ---------------- Prologue: step-0 partials + coefs for iteration 0 ----------------
    float lr_c = lr0;                                  // lr_t
    float cW   = 1.0f;                                 // cW_t
    float cWn  = fmaf(-lr_c, spwd, 1.0f);              // cW_{t+1}
    float icWn = __fdividef(1.0f, cWn);                // 1/cW_{t+1}
    float qlp  = s_q[0] * itq;
    {
        const ull x2  = bcast2(s_n[0]);                // x_0 = noise_0 (u=e=0)
        const ull cq2 = bcast2(qsc * qlp);
        ull ah0 = 0ull, ah1 = 0ull;
        #pragma unroll
        for (int k = 0; k < PAIRS; ++k) {
            ull h = relu2(fma2(win2[k], x2, fma2(cq2, wiq2[k], bia2[k])));
            hv[k] = h;
            if (k & 1) ah1 = fma2(h, h, ah1); else ah0 = fma2(h, h, ah0);
        }
        float2 f2 = unpack2(add2(ah0, ah1));
        float ah_s = f2.x + f2.y;
        float au_s = 0.0f;
        #pragma unroll
        for (int off = 16; off >= 4; off >>= 1) {
            au_s += __shfl_xor_sync(0xFFFFFFFFu, au_s, off);
            ah_s += __shfl_xor_sync(0xFFFFFFFFu, ah_s, off);
        }
        if (lane < 4) s_p[0][(wid << 2) | lane] = pack2(au_s, ah_s);  // au_0 = 0
    }
    // Coefficients for iteration 0 (step-0; ylp_{-1}=elp_{-1}=0, cW=1).
    const float4 yc0 = s_yc[0];
    float axc_c  = yc0.x;            // ay * cW
    float aec_c  = yc0.y;            // ae * cW
    float be_c   = yc0.z;            // by + byl(=0)
    float if_c   = yc0.w;
    float bx_c   = be_c + s_n[1];
    float belp_c = 0.0f;
    float lic_c  = lr_c * icWn;
    // cq for step 1 (A2 prep happens at loop top, in the LDS shadow).
    qlp = fmaf(ctq, qlp, s_q[1] * itq);
    ull cq2_c = bcast2(qsc * qlp);

    __syncthreads();   // s_p[0] visible; NOTHING between STS and this bar

    #pragma unroll 2
    for (int t = 0; t < T_STEPS; ++t) {
        const int buf = t & 1;

        // --- Combine step-t partials (8 LDS.128 first; A2 prep fills the wait). ---
        const longlong2* pp = reinterpret_cast<const longlong2*>(s_p[buf]);
        longlong2 l0 = pp[0], l1 = pp[1], l2 = pp[2], l3 = pp[3];
        longlong2 l4 = pp[4], l5 = pp[5], l6 = pp[6], l7 = pp[7];

        #pragma unroll
        for (int k = 0; k < PAIRS; ++k) A2[k] = fma2(cq2_c, wiq2[k], bia2[k]);

        ull r0 = add2(add2((ull)l0.x, (ull)l0.y), add2((ull)l1.x, (ull)l1.y));
        ull r1 = add2(add2((ull)l2.x, (ull)l2.y), add2((ull)l3.x, (ull)l3.y));
        ull r2 = add2(add2((ull)l4.x, (ull)l4.y), add2((ull)l5.x, (ull)l5.y));
        ull r3 = add2(add2((ull)l6.x, (ull)l6.y), add2((ull)l7.x, (ull)l7.y));
        float2 s = unpack2(add2(add2(r0, r1), add2(r2, r3)));
        const float sumu = s.x, sumh = s.y;

        // --- Short affine chains off sumu (coefs prepped last iteration). ---
        const float en   = fmaf(aec_c, sumu, be_c);     // e_t
        const float elpn = fmaf(ite, en, belp_c);       // elp_t
        const ull leoc2  = bcast2(lic_c * elpn);        // W-update coeff
        const ull x2     = bcast2(fmaf(axc_c, sumu, bx_c));   // x_{t+1}

        // --- Hot loop: W_{t+1}, h_{t+1}, partial dot/sumsq (fused). ---
        ull au0 = 0ull, au1 = 0ull, ah0 = 0ull, ah1 = 0ull;
        #pragma unroll
        for (int k = 0; k < PAIRS; ++k) {
            W2[k] = fma2(leoc2, hv[k], W2[k]);
            ull h = relu2(fma2(win2[k], x2, A2[k]));
            hv[k] = h;
            if (k & 1) { au1 = fma2(W2[k], h, au1); ah1 = fma2(h, h, ah1); }
            else       { au0 = fma2(W2[k], h, au0); ah0 = fma2(h, h, ah0); }
        }
        float2 auf = unpack2(add2(au0, au1));
        float2 ahf = unpack2(add2(ah0, ah1));
        float au_s = auf.x + auf.y;
        float ah_s = ahf.x + ahf.y;

        // --- 3-level butterfly; lanes 0-3 hold the 4 residue classes. ---
        #pragma unroll
        for (int off = 16; off >= 4; off >>= 1) {
            au_s += __shfl_xor_sync(0xFFFFFFFFu, au_s, off);
            ah_s += __shfl_xor_sync(0xFFFFFFFFu, ah_s, off);
        }

        // --- Lean tail (fits the shfl shadow; y-algebra pre-staged in s_yc). ---
        const float un = cW * sumu;                     // u_t
        if (tid == 0) out[t * BSZ + b] = osc * un;
        const float ylpn = fmaf(if_c, un, be_c);        // ylp_t
        const float le = lr_c * elpn;
        const float v  = fmaf(le * le, sumh, FUDGE_C);
        float nrm; asm("sqrt.approx.f32 %0, %1;" : "=f"(nrm) : "f"(v));
        lr_c *= __expf(-lrd * nrm);                     // lr_{t+1}
        cW   = cWn;                                     // cW_{t+1}
        cWn  = cW * fmaf(-lr_c, spwd, 1.0f);            // cW_{t+2}
        icWn = __fdividef(1.0f, cWn);
        // Coefficients for iteration t+1 (padded arrays: no clamps).
        const float byl = cty * ylpn;
        const float4 yc = s_yc[t + 1];
        axc_c  = yc.x * cW;
        aec_c  = yc.y * cW;
        be_c   = yc.z + byl;
        if_c   = yc.w;
        bx_c   = be_c + s_n[t + 2];
        belp_c = cte * elpn;
        lic_c  = lr_c * icWn;
        qlp    = fmaf(ctq, qlp, s_q[t + 2] * itq);      // qlp_{t+2}
        cq2_c  = bcast2(qsc * qlp);

        // --- STS then bar: nothing between them. ---
        if (lane < 4) s_p[buf ^ 1][(wid << 2) | lane] = pack2(au_s, ah_s);
        __syncthreads();
    }
}

extern "C" void kernel_launch(void* const* d_in, const int* in_sizes, int n_in,
                              void* d_out, int out_size)
{
    const float* noises = (const float*)d_in[1];
    const float* ys     = (const float*)d_in[2];
    const float* qs     = (const float*)d_in[3];
    const float* zb     = (const float*)d_in[4];
    const float* w_in   = (const float*)d_in[5];
    const float* w_inq  = (const float*)d_in[6];

    elbo_scan_kernel<<<BSZ, BLOCK>>>(noises, ys, qs, zb, w_in, w_inq,
                                     (const float*)d_in[7],  (const float*)d_in[8],
                                     (const float*)d_in[9],  (const float*)d_in[10],
                                     (const float*)d_in[11], (const float*)d_in[12],
                                     (const float*)d_in[13], (const float*)d_in[14],
                                     (const float*)d_in[15], (const float*)d_in[16],
                                     (float*)d_out);
}